// round 16
// baseline (speedup 1.0000x reference)
#include <cuda_runtime.h>
#include <cuda_fp16.h>
#include <cstdint>

// SGConv: out = relu( (A @ ((x@W) * norm_src)) * norm_dst + b )
// B=4, N=16384, D=128, E=1048576
#define Bc   4
#define Nc   16384
#define Dc   128
#define BNc  (Bc * Nc)      // 65536 nodes
#define EMAX (1 << 20)
#define SCAN_BLOCKS 256     // 256 blocks x 256 threads = 65536
#define GEMM_BLOCKS (BNc / 128)   // 512
#define HIST_BLOCKS 512

// ---- scratch (static device globals; no allocation) ----
// NOTE: g_cnt/g_deg are zeroed at the END of k_scatter (state restoration for
// the next graph replay); module-load zero-init covers the first call.
__device__ __half2 g_yh[(size_t)BNc * 64]; // 16 MB: support = x@W, fp16
__device__ float g_deg[BNc];
__device__ float g_norm[BNc];
__device__ int   g_cnt[BNc];
__device__ int   g_off[BNc + 1];
__device__ int   g_rank[EMAX];            // within-destination edge rank
__device__ int2  g_edge[EMAX];            // CSR-sorted (src, val*norm[src])
__device__ int   g_blksum[SCAN_BLOCKS];   // per-block count totals

// ---- packed f32x2 helpers (FFMA2 path; ptxas won't auto-fuse) ----
__device__ __forceinline__ unsigned long long pack2(float lo, float hi) {
    unsigned long long r;
    asm("mov.b64 %0, {%1, %2};" : "=l"(r) : "f"(lo), "f"(hi));
    return r;
}
__device__ __forceinline__ void unpack2(unsigned long long v, float& lo, float& hi) {
    asm("mov.b64 {%0, %1}, %2;" : "=f"(lo), "=f"(hi) : "l"(v));
}
__device__ __forceinline__ void fma2(unsigned long long& d, unsigned long long a,
                                     unsigned long long b) {
    asm("fma.rn.f32x2 %0, %1, %2, %0;" : "+l"(d) : "l"(a), "l"(b));
}

// ---------------------------------------------------------------------------
// Fused GEMM + histogram (heterogeneous grid).
// Blocks [0, GEMM_BLOCKS): g_yh = half(x @ W), 128x128 tile, 8x8 thread tile.
//   f32x2 pairs run along M: A-pairs are adjacent smem floats (loaded as
//   64-bit lanes of LDS.128, zero MOVs) and Ws is staged PRE-DUPLICATED
//   ((b,b) as u64) so B operands also come straight from LDS.128. Mainloop
//   per k per thread: 6 LDS + 32 FFMA2, no pack MOVs. K-chunk 16 keeps smem
//   at 24.8 KB (occupancy for both grid paths).
// Blocks [GEMM_BLOCKS, ...): grid-stride histogram; records each edge's
//   within-destination rank (atomicAdd return) so scatter needs no atomics.
__global__ void __launch_bounds__(256) k_gemm_hist(
        const float* __restrict__ x, const float* __restrict__ W,
        const int* __restrict__ eb, const int* __restrict__ er,
        const float* __restrict__ ev, int E) {
    __shared__ float Xs[16][132];              // [k][m], 8.4 KB
    __shared__ unsigned long long Ws2[16][128]; // [k][n] dup pairs, 16 KB

    if (blockIdx.x >= GEMM_BLOCKS) {
        // -------- histogram path (grid-stride) --------
        int start = (blockIdx.x - GEMM_BLOCKS) * 256 + threadIdx.x;
        for (int e = start; e < E; e += HIST_BLOCKS * 256) {
            int dst = eb[e] * Nc + er[e];
            atomicAdd(&g_deg[dst], fabsf(ev[e]));
            g_rank[e] = atomicAdd(&g_cnt[dst], 1);
        }
        return;
    }

    // -------- GEMM path --------
    int tid  = threadIdx.x;
    int row0 = blockIdx.x * 128;
    int tx = tid & 15, ty = tid >> 4;
    int m0 = ty * 8, n0 = tx * 8;

    // acc2[i2][j] = (out[m0+2*i2][n0+j], out[m0+2*i2+1][n0+j]) packed f32x2
    unsigned long long acc2[4][8];
#pragma unroll
    for (int i = 0; i < 4; i++)
#pragma unroll
        for (int j = 0; j < 8; j++) acc2[i][j] = 0ull;

    const float4* x4 = reinterpret_cast<const float4*>(x);
    const float4* W4 = reinterpret_cast<const float4*>(W);

    for (int kk = 0; kk < 128; kk += 16) {
        // stage X transposed [k][m]: thread reads float4 (4 k's, one m-row)
#pragma unroll
        for (int q = 0; q < 2; q++) {
            int idx = tid + 256 * q;
            int r  = idx >> 2;          // m within tile (0..127)
            int kq = idx & 3;           // which float4 along k (16/4)
            float4 v = x4[(size_t)(row0 + r) * 32 + (kk >> 2) + kq];
            Xs[kq * 4 + 0][r] = v.x;
            Xs[kq * 4 + 1][r] = v.y;
            Xs[kq * 4 + 2][r] = v.z;
            Xs[kq * 4 + 3][r] = v.w;
        }
        // stage W duplicated: Ws2[k][n] = (W[kk+k][n], W[kk+k][n])
#pragma unroll
        for (int q = 0; q < 2; q++) {
            int idx = tid + 256 * q;
            int k  = idx >> 5;          // 0..15
            int n4 = idx & 31;
            float4 v = W4[(size_t)(kk + k) * 32 + n4];
            Ws2[k][n4 * 4 + 0] = pack2(v.x, v.x);
            Ws2[k][n4 * 4 + 1] = pack2(v.y, v.y);
            Ws2[k][n4 * 4 + 2] = pack2(v.z, v.z);
            Ws2[k][n4 * 4 + 3] = pack2(v.w, v.w);
        }
        __syncthreads();

#pragma unroll
        for (int k = 0; k < 16; k++) {
            const ulonglong2* ap =
                reinterpret_cast<const ulonglong2*>(&Xs[k][m0]);
            const ulonglong2* bp =
                reinterpret_cast<const ulonglong2*>(&Ws2[k][n0]);
            ulonglong2 a01 = ap[0], a23 = ap[1];
            ulonglong2 b01 = bp[0], b23 = bp[1], b45 = bp[2], b67 = bp[3];
            unsigned long long a[4] = {a01.x, a01.y, a23.x, a23.y};
            unsigned long long b[8] = {b01.x, b01.y, b23.x, b23.y,
                                       b45.x, b45.y, b67.x, b67.y};
#pragma unroll
            for (int i = 0; i < 4; i++)
#pragma unroll
                for (int j = 0; j < 8; j++)
                    fma2(acc2[i][j], a[i], b[j]);
        }
        __syncthreads();
    }

    // epilogue: each acc pair holds (row m0+2i, row m0+2i+1) for one column
#pragma unroll
    for (int i = 0; i < 4; i++) {
        float lo[8], hi[8];
#pragma unroll
        for (int j = 0; j < 8; j++) unpack2(acc2[i][j], lo[j], hi[j]);
        uint4 u0, u1;
        __half2 h;
        h = __floats2half2_rn(lo[0], lo[1]); u0.x = reinterpret_cast<const unsigned&>(h);
        h = __floats2half2_rn(lo[2], lo[3]); u0.y = reinterpret_cast<const unsigned&>(h);
        h = __floats2half2_rn(lo[4], lo[5]); u0.z = reinterpret_cast<const unsigned&>(h);
        h = __floats2half2_rn(lo[6], lo[7]); u0.w = reinterpret_cast<const unsigned&>(h);
        h = __floats2half2_rn(hi[0], hi[1]); u1.x = reinterpret_cast<const unsigned&>(h);
        h = __floats2half2_rn(hi[2], hi[3]); u1.y = reinterpret_cast<const unsigned&>(h);
        h = __floats2half2_rn(hi[4], hi[5]); u1.z = reinterpret_cast<const unsigned&>(h);
        h = __floats2half2_rn(hi[6], hi[7]); u1.w = reinterpret_cast<const unsigned&>(h);
        *reinterpret_cast<uint4*>(
            &g_yh[(size_t)(row0 + m0 + 2 * i) * 64 + (n0 >> 1)]) = u0;
        *reinterpret_cast<uint4*>(
            &g_yh[(size_t)(row0 + m0 + 2 * i + 1) * 64 + (n0 >> 1)]) = u1;
    }
}

// ---------------------------------------------------------------------------
// Parallel scan over g_cnt (65536 ints), fully coalesced.
// Phase A: per-block sums.
__global__ void __launch_bounds__(256) k_scanA() {
    __shared__ int sh[256];
    int t = threadIdx.x;
    int i = blockIdx.x * 256 + t;
    sh[t] = g_cnt[i];
    __syncthreads();
#pragma unroll
    for (int off = 128; off > 0; off >>= 1) {
        if (t < off) sh[t] += sh[t + off];
        __syncthreads();
    }
    if (t == 0) g_blksum[blockIdx.x] = sh[0];
}

// Phase BC (merged): every block redundantly scans the 256 block sums in smem
// to derive its own offset, then does its local exclusive scan + norm.
__global__ void __launch_bounds__(256) k_scanBC() {
    __shared__ int bs[256];
    __shared__ int sh[256];
    int t = threadIdx.x;

    bs[t] = g_blksum[t];
    __syncthreads();
    for (int off = 1; off < 256; off <<= 1) {
        int u = (t >= off) ? bs[t - off] : 0;
        __syncthreads();
        bs[t] += u;
        __syncthreads();
    }
    int blkoff = (blockIdx.x > 0) ? bs[blockIdx.x - 1] : 0;
    if (blockIdx.x == 0 && t == 0) g_off[BNc] = bs[255];

    int i = blockIdx.x * 256 + t;
    int c = g_cnt[i];
    sh[t] = c;
    __syncthreads();
    for (int off = 1; off < 256; off <<= 1) {
        int u = (t >= off) ? sh[t - off] : 0;
        __syncthreads();
        sh[t] += u;
        __syncthreads();
    }
    g_off[i] = blkoff + sh[t] - c;     // exclusive prefix
    g_norm[i] = rsqrtf(g_deg[i] + 1e-6f);
}

// ---------------------------------------------------------------------------
// scatter edges into CSR order (atomic-free: precomputed rank); fold the
// source-side norm into the edge value; pack (src, val) into ONE int2 store.
// Tail: restore g_cnt/g_deg to zero for the next graph replay.
__global__ void k_scatter(const int* __restrict__ eb, const int* __restrict__ er,
                          const int* __restrict__ ec, const float* __restrict__ ev,
                          int E) {
    int e = blockIdx.x * blockDim.x + threadIdx.x;
    if (e < E) {
        int b   = eb[e];
        int dst = b * Nc + er[e];
        int src = b * Nc + ec[e];
        int pos = g_off[dst] + g_rank[e];
        float v = ev[e] * g_norm[src];
        g_edge[pos] = make_int2(src, __float_as_int(v));
    }
    if (e < BNc) { g_cnt[e] = 0; g_deg[e] = 0.f; }
}

// ---------------------------------------------------------------------------
// SpMM + epilogue: one warp per destination node. Each edge is read by ALL
// lanes at the SAME address (uniform LDG.64, broadcast line) — no SHFL, no
// staging, no chunk predication. 32-bit y indexing (fits: 64K rows x 32).
__global__ void __launch_bounds__(256) k_spmm(const float* __restrict__ bias,
                                              float* __restrict__ out) {
    int w    = (blockIdx.x * 256 + threadIdx.x) >> 5;
    int lane = threadIdx.x & 31;
    if (w >= BNc) return;

    int s = g_off[w];
    int e = g_off[w + 1];
    const uint2* y2 = reinterpret_cast<const uint2*>(g_yh);  // 32 uint2/row

    float4 acc = make_float4(0.f, 0.f, 0.f, 0.f);
    int j = s;
    for (; j + 4 <= e; j += 4) {
        int2 e0 = g_edge[j];
        int2 e1 = g_edge[j + 1];
        int2 e2 = g_edge[j + 2];
        int2 e3 = g_edge[j + 3];
        uint2 r0 = y2[((unsigned)e0.x << 5) | lane];
        uint2 r1 = y2[((unsigned)e1.x << 5) | lane];
        uint2 r2 = y2[((unsigned)e2.x << 5) | lane];
        uint2 r3 = y2[((unsigned)e3.x << 5) | lane];
        float v0 = __int_as_float(e0.y);
        float v1 = __int_as_float(e1.y);
        float v2 = __int_as_float(e2.y);
        float v3 = __int_as_float(e3.y);
        float2 a0 = __half22float2(reinterpret_cast<const __half2&>(r0.x));
        float2 b0 = __half22float2(reinterpret_cast<const __half2&>(r0.y));
        float2 a1 = __half22float2(reinterpret_cast<const __half2&>(r1.x));
        float2 b1 = __half22float2(reinterpret_cast<const __half2&>(r1.y));
        float2 a2 = __half22float2(reinterpret_cast<const __half2&>(r2.x));
        float2 b2 = __half22float2(reinterpret_cast<const __half2&>(r2.y));
        float2 a3 = __half22float2(reinterpret_cast<const __half2&>(r3.x));
        float2 b3 = __half22float2(reinterpret_cast<const __half2&>(r3.y));
        acc.x = fmaf(v0, a0.x, acc.x);
        acc.y = fmaf(v0, a0.y, acc.y);
        acc.z = fmaf(v0, b0.x, acc.z);
        acc.w = fmaf(v0, b0.y, acc.w);
        acc.x = fmaf(v1, a1.x, acc.x);
        acc.y = fmaf(v1, a1.y, acc.y);
        acc.z = fmaf(v1, b1.x, acc.z);
        acc.w = fmaf(v1, b1.y, acc.w);
        acc.x = fmaf(v2, a2.x, acc.x);
        acc.y = fmaf(v2, a2.y, acc.y);
        acc.z = fmaf(v2, b2.x, acc.z);
        acc.w = fmaf(v2, b2.y, acc.w);
        acc.x = fmaf(v3, a3.x, acc.x);
        acc.y = fmaf(v3, a3.y, acc.y);
        acc.z = fmaf(v3, b3.x, acc.z);
        acc.w = fmaf(v3, b3.y, acc.w);
    }
    for (; j < e; j++) {
        int2 ee = g_edge[j];
        float v = __int_as_float(ee.y);
        uint2 r = y2[((unsigned)ee.x << 5) | lane];
        float2 a = __half22float2(reinterpret_cast<const __half2&>(r.x));
        float2 b = __half22float2(reinterpret_cast<const __half2&>(r.y));
        acc.x = fmaf(v, a.x, acc.x);
        acc.y = fmaf(v, a.y, acc.y);
        acc.z = fmaf(v, b.x, acc.z);
        acc.w = fmaf(v, b.y, acc.w);
    }

    float nrm = g_norm[w];
    float4 bv = reinterpret_cast<const float4*>(bias)[lane];
    float4 o;
    o.x = fmaxf(fmaf(acc.x, nrm, bv.x), 0.f);
    o.y = fmaxf(fmaf(acc.y, nrm, bv.y), 0.f);
    o.z = fmaxf(fmaf(acc.z, nrm, bv.z), 0.f);
    o.w = fmaxf(fmaf(acc.w, nrm, bv.w), 0.f);
    reinterpret_cast<float4*>(out)[(size_t)w * 32 + lane] = o;
}

// ---------------------------------------------------------------------------
extern "C" void kernel_launch(void* const* d_in, const int* in_sizes, int n_in,
                              void* d_out, int out_size) {
    const float* x  = (const float*)d_in[0];   // [B,N,D]
    const float* W  = (const float*)d_in[1];   // [D,D]
    const float* bb = (const float*)d_in[2];   // [D]
    const int*   eb = (const int*)d_in[3];     // [E]
    const int*   er = (const int*)d_in[4];     // [E]
    const int*   ec = (const int*)d_in[5];     // [E]
    const float* ev = (const float*)d_in[6];   // [E]
    int E = in_sizes[3];

    float* out = (float*)d_out;

    k_gemm_hist<<<GEMM_BLOCKS + HIST_BLOCKS, 256>>>(x, W, eb, er, ev, E);
    k_scanA<<<SCAN_BLOCKS, 256>>>();
    k_scanBC<<<SCAN_BLOCKS, 256>>>();
    k_scatter<<<(E + 255) / 256, 256>>>(eb, er, ec, ev, E);
    k_spmm<<<(BNc * 32) / 256, 256>>>(bb, out);
}

// round 17
// speedup vs baseline: 1.9030x; 1.9030x over previous
#include <cuda_runtime.h>
#include <cuda_fp16.h>
#include <cstdint>

// SGConv: out = relu( (A @ ((x@W) * norm_src)) * norm_dst + b )
// B=4, N=16384, D=128, E=1048576
#define Bc   4
#define Nc   16384
#define Dc   128
#define BNc  (Bc * Nc)      // 65536 nodes
#define EMAX (1 << 20)
#define SCAN_BLOCKS 256     // 256 blocks x 256 threads = 65536
#define GEMM_BLOCKS (BNc / 128)   // 512
#define HIST_BLOCKS 512

// ---- scratch (static device globals; no allocation) ----
// NOTE: g_cnt/g_deg are zeroed at the END of k_scatter (state restoration for
// the next graph replay); module-load zero-init covers the first call.
__device__ __half2 g_yh[(size_t)BNc * 64]; // 16 MB: support = x@W, fp16
__device__ float g_deg[BNc];
__device__ float g_norm[BNc];
__device__ int   g_cnt[BNc];
__device__ int   g_off[BNc + 1];
__device__ int   g_rank[EMAX];            // within-destination edge rank
__device__ int2  g_edge[EMAX];            // CSR-sorted (src, val*norm[src])
__device__ int   g_blksum[SCAN_BLOCKS];   // per-block count totals

// ---- packed f32x2 helpers (FFMA2 path; ptxas won't auto-fuse) ----
__device__ __forceinline__ unsigned long long pack2(float lo, float hi) {
    unsigned long long r;
    asm("mov.b64 %0, {%1, %2};" : "=l"(r) : "f"(lo), "f"(hi));
    return r;
}
__device__ __forceinline__ void unpack2(unsigned long long v, float& lo, float& hi) {
    asm("mov.b64 {%0, %1}, %2;" : "=f"(lo), "=f"(hi) : "l"(v));
}
__device__ __forceinline__ void fma2(unsigned long long& d, unsigned long long a,
                                     unsigned long long b) {
    asm("fma.rn.f32x2 %0, %1, %2, %0;" : "+l"(d) : "l"(a), "l"(b));
}

// ---------------------------------------------------------------------------
// Fused GEMM + histogram (heterogeneous grid). EXACTLY the R13 GEMM (best
// measured config: 107.0 us total) — do not rewrite without SASS evidence.
// Blocks [0, GEMM_BLOCKS): g_yh = half(x @ W) (128x128 tile, 8x8 thread tile,
//   packed f32x2 FMA). Xs stored TRANSPOSED [k][m]: per-k A-read is 2x LDS.128.
// Blocks [GEMM_BLOCKS, ...): grid-stride histogram; records each edge's
//   within-destination rank (atomicAdd return) so scatter needs no atomics.
__global__ void __launch_bounds__(256) k_gemm_hist(
        const float* __restrict__ x, const float* __restrict__ W,
        const int* __restrict__ eb, const int* __restrict__ er,
        const float* __restrict__ ev, int E) {
    __shared__ float Xs[32][132];   // [k][m], stride 132 keeps 16B alignment
    __shared__ float Ws[32][128];   // [k][n]

    if (blockIdx.x >= GEMM_BLOCKS) {
        // -------- histogram path (grid-stride) --------
        int start = (blockIdx.x - GEMM_BLOCKS) * 256 + threadIdx.x;
        for (int e = start; e < E; e += HIST_BLOCKS * 256) {
            int dst = eb[e] * Nc + er[e];
            atomicAdd(&g_deg[dst], fabsf(ev[e]));
            g_rank[e] = atomicAdd(&g_cnt[dst], 1);
        }
        return;
    }

    // -------- GEMM path --------
    int tid  = threadIdx.x;
    int row0 = blockIdx.x * 128;
    int tx = tid & 15, ty = tid >> 4;
    int m0 = ty * 8, n0 = tx * 8;

    unsigned long long acc2[8][4];
#pragma unroll
    for (int i = 0; i < 8; i++)
#pragma unroll
        for (int j = 0; j < 4; j++) acc2[i][j] = 0ull;

    const float4* x4 = reinterpret_cast<const float4*>(x);
    const float4* W4 = reinterpret_cast<const float4*>(W);

    for (int kk = 0; kk < 128; kk += 32) {
#pragma unroll
        for (int q = 0; q < 4; q++) {
            int idx = tid + 256 * q;
            int r  = idx >> 3;          // m within tile
            int kq = idx & 7;           // which float4 along k
            float4 v = x4[(size_t)(row0 + r) * 32 + (kk >> 2) + kq];
            Xs[kq * 4 + 0][r] = v.x;
            Xs[kq * 4 + 1][r] = v.y;
            Xs[kq * 4 + 2][r] = v.z;
            Xs[kq * 4 + 3][r] = v.w;
        }
#pragma unroll
        for (int q = 0; q < 4; q++) {
            int idx = tid + 256 * q;
            int k  = idx >> 5;
            int n4 = idx & 31;
            float4 v = W4[(size_t)(kk + k) * 32 + n4];
            *reinterpret_cast<float4*>(&Ws[k][n4 * 4]) = v;
        }
        __syncthreads();

#pragma unroll
        for (int k = 0; k < 32; k++) {
            float4 a0 = *reinterpret_cast<const float4*>(&Xs[k][m0]);
            float4 a1 = *reinterpret_cast<const float4*>(&Xs[k][m0 + 4]);
            float4 b0 = *reinterpret_cast<const float4*>(&Ws[k][n0]);
            float4 b1 = *reinterpret_cast<const float4*>(&Ws[k][n0 + 4]);
            unsigned long long bp[4];
            bp[0] = pack2(b0.x, b0.y);
            bp[1] = pack2(b0.z, b0.w);
            bp[2] = pack2(b1.x, b1.y);
            bp[3] = pack2(b1.z, b1.w);
            float av[8] = {a0.x, a0.y, a0.z, a0.w, a1.x, a1.y, a1.z, a1.w};
#pragma unroll
            for (int i = 0; i < 8; i++) {
                unsigned long long a2 = pack2(av[i], av[i]);
                fma2(acc2[i][0], a2, bp[0]);
                fma2(acc2[i][1], a2, bp[1]);
                fma2(acc2[i][2], a2, bp[2]);
                fma2(acc2[i][3], a2, bp[3]);
            }
        }
        __syncthreads();
    }

#pragma unroll
    for (int i = 0; i < 8; i++) {
        float o[8];
#pragma unroll
        for (int j = 0; j < 4; j++) unpack2(acc2[i][j], o[2 * j], o[2 * j + 1]);
        __half2 h0 = __floats2half2_rn(o[0], o[1]);
        __half2 h1 = __floats2half2_rn(o[2], o[3]);
        __half2 h2 = __floats2half2_rn(o[4], o[5]);
        __half2 h3 = __floats2half2_rn(o[6], o[7]);
        uint4 u;
        u.x = reinterpret_cast<const unsigned&>(h0);
        u.y = reinterpret_cast<const unsigned&>(h1);
        u.z = reinterpret_cast<const unsigned&>(h2);
        u.w = reinterpret_cast<const unsigned&>(h3);
        *reinterpret_cast<uint4*>(
            &g_yh[(size_t)(row0 + m0 + i) * 64 + (n0 >> 1)]) = u;
    }
}

// ---------------------------------------------------------------------------
// Parallel scan over g_cnt (65536 ints), fully coalesced.
// Phase A: per-block sums.
__global__ void __launch_bounds__(256) k_scanA() {
    __shared__ int sh[256];
    int t = threadIdx.x;
    int i = blockIdx.x * 256 + t;
    sh[t] = g_cnt[i];
    __syncthreads();
#pragma unroll
    for (int off = 128; off > 0; off >>= 1) {
        if (t < off) sh[t] += sh[t + off];
        __syncthreads();
    }
    if (t == 0) g_blksum[blockIdx.x] = sh[0];
}

// Phase BC (merged): every block redundantly scans the 256 block sums in smem
// to derive its own offset, then does its local exclusive scan + norm.
__global__ void __launch_bounds__(256) k_scanBC() {
    __shared__ int bs[256];
    __shared__ int sh[256];
    int t = threadIdx.x;

    bs[t] = g_blksum[t];
    __syncthreads();
    for (int off = 1; off < 256; off <<= 1) {
        int u = (t >= off) ? bs[t - off] : 0;
        __syncthreads();
        bs[t] += u;
        __syncthreads();
    }
    int blkoff = (blockIdx.x > 0) ? bs[blockIdx.x - 1] : 0;
    if (blockIdx.x == 0 && t == 0) g_off[BNc] = bs[255];

    int i = blockIdx.x * 256 + t;
    int c = g_cnt[i];
    sh[t] = c;
    __syncthreads();
    for (int off = 1; off < 256; off <<= 1) {
        int u = (t >= off) ? sh[t - off] : 0;
        __syncthreads();
        sh[t] += u;
        __syncthreads();
    }
    g_off[i] = blkoff + sh[t] - c;     // exclusive prefix
    g_norm[i] = rsqrtf(g_deg[i] + 1e-6f);
}

// ---------------------------------------------------------------------------
// scatter edges into CSR order (atomic-free: precomputed rank); fold the
// source-side norm into the edge value; pack (src, val) into ONE int2 store.
// Tail: restore g_cnt/g_deg to zero for the next graph replay.
__global__ void k_scatter(const int* __restrict__ eb, const int* __restrict__ er,
                          const int* __restrict__ ec, const float* __restrict__ ev,
                          int E) {
    int e = blockIdx.x * blockDim.x + threadIdx.x;
    if (e < E) {
        int b   = eb[e];
        int dst = b * Nc + er[e];
        int src = b * Nc + ec[e];
        int pos = g_off[dst] + g_rank[e];
        float v = ev[e] * g_norm[src];
        g_edge[pos] = make_int2(src, __float_as_int(v));
    }
    if (e < BNc) { g_cnt[e] = 0; g_deg[e] = 0.f; }
}

// ---------------------------------------------------------------------------
// SpMM + epilogue: one warp per destination node. THE ONE DELTA vs R13:
// each edge is read by ALL lanes at the SAME address (uniform LDG.64 ->
// broadcast L1 wavefront, line reused across the node's edges) instead of
// the 32-edge SHFL-broadcast chunking — removes 2 SHFL/edge and the chunk
// staging/predication, same register footprint.
__global__ void __launch_bounds__(256) k_spmm(const float* __restrict__ bias,
                                              float* __restrict__ out) {
    int w    = (blockIdx.x * 256 + threadIdx.x) >> 5;
    int lane = threadIdx.x & 31;
    if (w >= BNc) return;

    int s = g_off[w];
    int e = g_off[w + 1];
    const uint2* y2 = reinterpret_cast<const uint2*>(g_yh);  // 32 uint2/row

    float4 acc = make_float4(0.f, 0.f, 0.f, 0.f);
    int j = s;
    for (; j + 4 <= e; j += 4) {
        int2 e0 = g_edge[j];
        int2 e1 = g_edge[j + 1];
        int2 e2 = g_edge[j + 2];
        int2 e3 = g_edge[j + 3];
        uint2 r0 = y2[((unsigned)e0.x << 5) | lane];
        uint2 r1 = y2[((unsigned)e1.x << 5) | lane];
        uint2 r2 = y2[((unsigned)e2.x << 5) | lane];
        uint2 r3 = y2[((unsigned)e3.x << 5) | lane];
        float v0 = __int_as_float(e0.y);
        float v1 = __int_as_float(e1.y);
        float v2 = __int_as_float(e2.y);
        float v3 = __int_as_float(e3.y);
        float2 a0 = __half22float2(reinterpret_cast<const __half2&>(r0.x));
        float2 b0 = __half22float2(reinterpret_cast<const __half2&>(r0.y));
        float2 a1 = __half22float2(reinterpret_cast<const __half2&>(r1.x));
        float2 b1 = __half22float2(reinterpret_cast<const __half2&>(r1.y));
        float2 a2 = __half22float2(reinterpret_cast<const __half2&>(r2.x));
        float2 b2 = __half22float2(reinterpret_cast<const __half2&>(r2.y));
        float2 a3 = __half22float2(reinterpret_cast<const __half2&>(r3.x));
        float2 b3 = __half22float2(reinterpret_cast<const __half2&>(r3.y));
        acc.x = fmaf(v0, a0.x, acc.x);
        acc.y = fmaf(v0, a0.y, acc.y);
        acc.z = fmaf(v0, b0.x, acc.z);
        acc.w = fmaf(v0, b0.y, acc.w);
        acc.x = fmaf(v1, a1.x, acc.x);
        acc.y = fmaf(v1, a1.y, acc.y);
        acc.z = fmaf(v1, b1.x, acc.z);
        acc.w = fmaf(v1, b1.y, acc.w);
        acc.x = fmaf(v2, a2.x, acc.x);
        acc.y = fmaf(v2, a2.y, acc.y);
        acc.z = fmaf(v2, b2.x, acc.z);
        acc.w = fmaf(v2, b2.y, acc.w);
        acc.x = fmaf(v3, a3.x, acc.x);
        acc.y = fmaf(v3, a3.y, acc.y);
        acc.z = fmaf(v3, b3.x, acc.z);
        acc.w = fmaf(v3, b3.y, acc.w);
    }
    for (; j < e; j++) {
        int2 ee = g_edge[j];
        float v = __int_as_float(ee.y);
        uint2 r = y2[((unsigned)ee.x << 5) | lane];
        float2 a = __half22float2(reinterpret_cast<const __half2&>(r.x));
        float2 b = __half22float2(reinterpret_cast<const __half2&>(r.y));
        acc.x = fmaf(v, a.x, acc.x);
        acc.y = fmaf(v, a.y, acc.y);
        acc.z = fmaf(v, b.x, acc.z);
        acc.w = fmaf(v, b.y, acc.w);
    }

    float nrm = g_norm[w];
    float4 bv = reinterpret_cast<const float4*>(bias)[lane];
    float4 o;
    o.x = fmaxf(fmaf(acc.x, nrm, bv.x), 0.f);
    o.y = fmaxf(fmaf(acc.y, nrm, bv.y), 0.f);
    o.z = fmaxf(fmaf(acc.z, nrm, bv.z), 0.f);
    o.w = fmaxf(fmaf(acc.w, nrm, bv.w), 0.f);
    reinterpret_cast<float4*>(out)[(size_t)w * 32 + lane] = o;
}

// ---------------------------------------------------------------------------
extern "C" void kernel_launch(void* const* d_in, const int* in_sizes, int n_in,
                              void* d_out, int out_size) {
    const float* x  = (const float*)d_in[0];   // [B,N,D]
    const float* W  = (const float*)d_in[1];   // [D,D]
    const float* bb = (const float*)d_in[2];   // [D]
    const int*   eb = (const int*)d_in[3];     // [E]
    const int*   er = (const int*)d_in[4];     // [E]
    const int*   ec = (const int*)d_in[5];     // [E]
    const float* ev = (const float*)d_in[6];   // [E]
    int E = in_sizes[3];

    float* out = (float*)d_out;

    k_gemm_hist<<<GEMM_BLOCKS + HIST_BLOCKS, 256>>>(x, W, eb, er, ev, E);
    k_scanA<<<SCAN_BLOCKS, 256>>>();
    k_scanBC<<<SCAN_BLOCKS, 256>>>();
    k_scatter<<<(E + 255) / 256, 256>>>(eb, er, ec, ev, E);
    k_spmm<<<(BNc * 32) / 256, 256>>>(bb, out);
}